// round 1
// baseline (speedup 1.0000x reference)
#include <cuda_runtime.h>
#include <cuda_bf16.h>
#include <cstddef>

// ---------------------------------------------------------------------------
// HGNN_conv: out = 0.5 * diag(D_e) * MT^T * diag(D_v) * MT * (x @ W)
//   x      [16384, 256]   fp32
//   W      [256, 128]     fp32
//   MT     [8192, 16384]  fp32
//   D_v    [8192]         fp32
//   D_e    [16384]        fp32
//   out    [16384, 128]   fp32
//
// R1 baseline: SIMT fp32 tiled GEMMs (BM=64, BN=128, BK=16, 128 thr, 8x8 reg
// tiles, float4 I/O), split-K with fp32 atomicAdd for the two big GEMMs.
// D_v folded into B-tile load of GEMM3, 0.5*D_e folded into A-tile load of
// GEMM3 so atomic accumulation commutes with the scalings.
// ---------------------------------------------------------------------------

#define N_NODES 16384
#define N_EDGES 8192
#define IN_FT   256
#define OUT_FT  128

// scratch (no cudaMalloc allowed)
__device__ float g_y [N_NODES * OUT_FT];   // 8 MB
__device__ float g_ey[N_EDGES * OUT_FT];   // 4 MB

#define BM 64
#define BN 128
#define BK 16
#define LDA_S 68   // padded stride for transposed A tile

__global__ void zero2_kernel(float* __restrict__ a, size_t na4,
                             float* __restrict__ b, size_t nb4) {
    size_t i = (size_t)blockIdx.x * blockDim.x + threadIdx.x;
    size_t stride = (size_t)gridDim.x * blockDim.x;
    float4 z = make_float4(0.f, 0.f, 0.f, 0.f);
    for (size_t j = i; j < na4; j += stride) reinterpret_cast<float4*>(a)[j] = z;
    for (size_t j = i; j < nb4; j += stride) reinterpret_cast<float4*>(b)[j] = z;
}

// A_TRANS = true : A stored [M, K] row-major (needs smem transpose)
// A_TRANS = false: A stored [K, M] row-major (direct, i.e. we compute A^T logic)
// ATOMIC  = true : atomicAdd epilogue (split-K)
template <bool A_TRANS, bool ATOMIC>
__global__ __launch_bounds__(128)
void gemm_k(const float* __restrict__ A,
            const float* __restrict__ B,       // [K, 128] row-major
            float*       __restrict__ C,       // [M, 128] row-major
            const float* __restrict__ b_row_scale, // [K] or null, scales B rows
            const float* __restrict__ a_col_scale, // [M] or null, scales output rows (folded into A)
            float alpha,                        // applied with a_col_scale
            int M, int K, int k_chunk)
{
    __shared__ float As[BK][LDA_S];
    __shared__ float Bs[BK][BN];

    const int tid  = threadIdx.x;
    const int trow = tid >> 4;   // 0..7
    const int tcol = tid & 15;   // 0..15
    const int m0   = blockIdx.x * BM;
    const int kb   = blockIdx.y * k_chunk;
    const int ke   = kb + k_chunk;

    float acc[8][8];
    #pragma unroll
    for (int i = 0; i < 8; ++i)
        #pragma unroll
        for (int j = 0; j < 8; ++j) acc[i][j] = 0.f;

    for (int kk = kb; kk < ke; kk += BK) {
        // ---- load A tile into As[k][m] ----
        if (A_TRANS) {
            #pragma unroll
            for (int p = 0; p < 2; ++p) {
                int idx = tid + p * 128;        // 0..255
                int m   = idx >> 2;             // 0..63
                int kq  = idx & 3;              // 0..3 (quad of 4 k's)
                const float4 v = *reinterpret_cast<const float4*>(
                    &A[(size_t)(m0 + m) * K + kk + kq * 4]);
                As[kq * 4 + 0][m] = v.x;
                As[kq * 4 + 1][m] = v.y;
                As[kq * 4 + 2][m] = v.z;
                As[kq * 4 + 3][m] = v.w;
            }
        } else {
            #pragma unroll
            for (int p = 0; p < 2; ++p) {
                int idx = tid + p * 128;
                int k   = idx >> 4;             // 0..15
                int c4  = idx & 15;             // 0..15 -> 4 floats each
                float4 v = *reinterpret_cast<const float4*>(
                    &A[(size_t)(kk + k) * M + m0 + c4 * 4]);
                if (a_col_scale) {
                    const float4 s = *reinterpret_cast<const float4*>(
                        &a_col_scale[m0 + c4 * 4]);
                    v.x *= alpha * s.x; v.y *= alpha * s.y;
                    v.z *= alpha * s.z; v.w *= alpha * s.w;
                }
                *reinterpret_cast<float4*>(&As[k][c4 * 4]) = v;
            }
        }
        // ---- load B tile into Bs[k][n] ----
        #pragma unroll
        for (int p = 0; p < 4; ++p) {
            int idx = tid + p * 128;            // 0..511
            int k   = idx >> 5;                 // 0..15
            int c4  = idx & 31;                 // 0..31
            float4 v = *reinterpret_cast<const float4*>(
                &B[(size_t)(kk + k) * BN + c4 * 4]);
            if (b_row_scale) {
                float s = b_row_scale[kk + k];
                v.x *= s; v.y *= s; v.z *= s; v.w *= s;
            }
            *reinterpret_cast<float4*>(&Bs[k][c4 * 4]) = v;
        }
        __syncthreads();

        // ---- compute ----
        #pragma unroll
        for (int k = 0; k < BK; ++k) {
            const float4 a0 = *reinterpret_cast<const float4*>(&As[k][trow * 4]);
            const float4 a1 = *reinterpret_cast<const float4*>(&As[k][32 + trow * 4]);
            const float4 b0 = *reinterpret_cast<const float4*>(&Bs[k][tcol * 4]);
            const float4 b1 = *reinterpret_cast<const float4*>(&Bs[k][64 + tcol * 4]);
            const float a[8] = {a0.x, a0.y, a0.z, a0.w, a1.x, a1.y, a1.z, a1.w};
            const float b[8] = {b0.x, b0.y, b0.z, b0.w, b1.x, b1.y, b1.z, b1.w};
            #pragma unroll
            for (int i = 0; i < 8; ++i)
                #pragma unroll
                for (int j = 0; j < 8; ++j)
                    acc[i][j] += a[i] * b[j];
        }
        __syncthreads();
    }

    // ---- epilogue ----
    #pragma unroll
    for (int i = 0; i < 8; ++i) {
        const int m = m0 + ((i < 4) ? (trow * 4 + i) : (32 + trow * 4 + (i - 4)));
        float* crow = C + (size_t)m * BN;
        if (ATOMIC) {
            #pragma unroll
            for (int j = 0; j < 8; ++j) {
                const int n = (j < 4) ? (tcol * 4 + j) : (64 + tcol * 4 + (j - 4));
                atomicAdd(&crow[n], acc[i][j]);
            }
        } else {
            float4 v0 = make_float4(acc[i][0], acc[i][1], acc[i][2], acc[i][3]);
            float4 v1 = make_float4(acc[i][4], acc[i][5], acc[i][6], acc[i][7]);
            *reinterpret_cast<float4*>(&crow[tcol * 4])      = v0;
            *reinterpret_cast<float4*>(&crow[64 + tcol * 4]) = v1;
        }
    }
}

extern "C" void kernel_launch(void* const* d_in, const int* in_sizes, int n_in,
                              void* d_out, int out_size) {
    // identify inputs by element count (robust to ordering)
    const float *x = nullptr, *w = nullptr, *mt = nullptr, *dv = nullptr, *de = nullptr;
    for (int i = 0; i < n_in; ++i) {
        switch (in_sizes[i]) {
            case N_NODES * IN_FT:  x  = (const float*)d_in[i]; break;  // 4194304
            case IN_FT * OUT_FT:   w  = (const float*)d_in[i]; break;  // 32768
            case 134217728:        mt = (const float*)d_in[i]; break;  // 8192*16384
            case N_EDGES:          dv = (const float*)d_in[i]; break;  // 8192
            case N_NODES:          de = (const float*)d_in[i]; break;  // 16384
        }
    }
    float* out = (float*)d_out;

    float *y_ptr = nullptr, *ey_ptr = nullptr;
    { void* p; cudaGetSymbolAddress(&p, g_y);  y_ptr  = (float*)p; }
    { void* p; cudaGetSymbolAddress(&p, g_ey); ey_ptr = (float*)p; }

    // zero atomic targets: g_ey and d_out
    zero2_kernel<<<512, 256>>>(ey_ptr, (size_t)(N_EDGES * OUT_FT) / 4,
                               out,    (size_t)(N_NODES * OUT_FT) / 4);

    // GEMM1: y = x @ W            [16384,256] @ [256,128]
    gemm_k<true, false><<<dim3(N_NODES / BM, 1), 128>>>(
        x, w, y_ptr, nullptr, nullptr, 1.0f, N_NODES, IN_FT, IN_FT);

    // GEMM2: ey_raw = MT @ y      [8192,16384] @ [16384,128], split-K=4
    {
        const int KSPLIT = 4;
        gemm_k<true, true><<<dim3(N_EDGES / BM, KSPLIT), 128>>>(
            mt, y_ptr, ey_ptr, nullptr, nullptr, 1.0f,
            N_EDGES, N_NODES, N_NODES / KSPLIT);
    }

    // GEMM3: out = (0.5*D_e) ⊙ ( MT^T @ (D_v ⊙ ey_raw) ), split-K=4
    {
        const int KSPLIT = 4;
        gemm_k<false, true><<<dim3(N_NODES / BM, KSPLIT), 128>>>(
            mt, ey_ptr, out, dv, de, 0.5f,
            N_NODES, N_EDGES, N_EDGES / KSPLIT);
    }
}